// round 13
// baseline (speedup 1.0000x reference)
#include <cuda_runtime.h>
#include <cuda_fp16.h>
#include <math.h>

// Problem constants
#define BB   2
#define CC   256
#define HH   48
#define WWI  48
#define HW   2304      // 48*48
#define HID  64
#define OHH  96
#define N1   9216      // 96*96
#define NK   9
#define RFf  11.0f
#define SCLQ 0.17677669529663687f   // 32^-0.5
#define SIN  0.49473684210526314f   // 47/95  (align_corners scale)

// ---------------- scratch (device globals; no allocation) ----------------
__device__ float  g_At[256 * 128];      // fused [Wq;Wk]*ln_g, TRANSPOSED [c][o]
__device__ float  g_s1[128];
__device__ float  g_s2[128];
__device__ float  g_q48[BB * 64 * HW];  // NCHW q at 48x48
__device__ float  g_kT[4 * HW * 32];    // [bg][hw][32]  NHWC per group, fp32
__device__ __half g_vTh[4 * HW * 128];  // [bg][hw][128] NHWC per group, fp16
__device__ float  g_qup[BB * 64 * N1];  // NCHW q at 96x96
__device__ float  g_t[4 * N1 * 32];     // offset-net hidden, NHWC [bg][p][c]
__device__ int4   g_ci[4 * NK * N1];    // corner indices (premult x32)
__device__ float4 g_cw[4 * NK * N1];    // corner bilinear weights

// ---------------- bilinear corner helper (grid_sample, zeros pad) --------
struct Corner { int i00, i01, i10, i11; float w00, w01, w10, w11; };
__device__ __forceinline__ Corner mk_corner(float iy, float ix) {
    Corner r;
    float yf = floorf(iy), xf = floorf(ix);
    float wy = iy - yf, wx = ix - xf;
    int y0 = (int)yf, x0 = (int)xf;
    float vy0 = (y0 >= 0 && y0 < 48) ? 1.f : 0.f;
    float vy1 = (y0 >= -1 && y0 < 47) ? 1.f : 0.f;
    float vx0 = (x0 >= 0 && x0 < 48) ? 1.f : 0.f;
    float vx1 = (x0 >= -1 && x0 < 47) ? 1.f : 0.f;
    int yc0 = min(max(y0, 0), 47),     yc1 = min(max(y0 + 1, 0), 47);
    int xc0 = min(max(x0, 0), 47),     xc1 = min(max(x0 + 1, 0), 47);
    r.i00 = yc0 * 48 + xc0; r.i01 = yc0 * 48 + xc1;
    r.i10 = yc1 * 48 + xc0; r.i11 = yc1 * 48 + xc1;
    r.w00 = (1.f - wy) * (1.f - wx) * vy0 * vx0;
    r.w01 = (1.f - wy) * wx        * vy0 * vx1;
    r.w10 = wy        * (1.f - wx) * vy1 * vx0;
    r.w11 = wy        * wx         * vy1 * vx1;
    return r;
}

// ---------------- 1. fold LN affine into projection weights --------------
__global__ void k_prep(const float* __restrict__ Wq, const float* __restrict__ Wk,
                       const float* __restrict__ lg, const float* __restrict__ lb) {
    int o = blockIdx.x;          // 0..127
    int c = threadIdx.x;         // 0..255
    const float* Wrow = (o < 64) ? (Wq + o * 256) : (Wk + (o - 64) * 256);
    float w = Wrow[c];
    float a = w * lg[c];
    g_At[c * 128 + o] = a;       // transposed store
    __shared__ float s1s[256], s2s[256];
    s1s[c] = a; s2s[c] = w * lb[c];
    __syncthreads();
    for (int st = 128; st; st >>= 1) {
        if (c < st) { s1s[c] += s1s[c + st]; s2s[c] += s2s[c + st]; }
        __syncthreads();
    }
    if (c == 0) { g_s1[o] = s1s[0]; g_s2[o] = s2s[0]; }
}

// ---------------- 2. V transpose to NHWC per group (fp16 store) ----------
__global__ void k_vt(const float* __restrict__ x) {  // grid (72,4,4), block (32,8)
    __shared__ float tile[32][33];
    int hwt = blockIdx.x * 32, ct = blockIdx.y * 32, bg = blockIdx.z;
    int b = bg >> 1, g = bg & 1;
    const float* src = x + ((size_t)b * 256 + g * 128 + ct) * HW;
    int tx = threadIdx.x, ty = threadIdx.y;
    #pragma unroll
    for (int j = 0; j < 4; j++) {
        int c = ty + j * 8;
        tile[c][tx] = src[(size_t)c * HW + hwt + tx];
    }
    __syncthreads();
    __half* dst = g_vTh + ((size_t)bg * HW + hwt) * 128 + ct;
    #pragma unroll
    for (int j = 0; j < 4; j++) {
        int r = ty + j * 8;
        dst[(size_t)r * 128 + tx] = __float2half(tile[tx][r]);
    }
}

// ---------------- 3. fused LN-stats + LN + Q/K projection (smem GEMM) ----
__global__ void __launch_bounds__(256) k_proj(const float* __restrict__ x) {
    __shared__ float xs[256 * 32];    // 32KB  [c][p]
    __shared__ float As[32 * 128];    // 16KB  weight chunk [c][o]
    __shared__ float smu[32], srs[32];
    __shared__ float rs_[8][32], rq_[8][32];
    int tid = threadIdx.x;
    int px0 = blockIdx.x * 32;
    int b = px0 / HW, hw0 = px0 - b * HW;
    const float* xb = x + (size_t)b * CC * HW;
    for (int idx = tid; idx < 8192; idx += 256) {
        int c = idx >> 5, p = idx & 31;
        xs[idx] = xb[(size_t)c * HW + hw0 + p];
    }
    __syncthreads();
    {
        int p = tid & 31, cg = tid >> 5;
        float s = 0.f, q = 0.f;
        #pragma unroll 8
        for (int i = 0; i < 32; i++) {
            float v = xs[(cg * 32 + i) * 32 + p];
            s += v; q += v * v;
        }
        rs_[cg][p] = s; rq_[cg][p] = q;
        __syncthreads();
        if (tid < 32) {
            float S = 0.f, Q = 0.f;
            #pragma unroll
            for (int g2 = 0; g2 < 8; g2++) { S += rs_[g2][tid]; Q += rq_[g2][tid]; }
            float mu = S * (1.f / 256.f);
            smu[tid] = mu;
            srs[tid] = rsqrtf(Q * (1.f / 256.f) - mu * mu + 1e-5f);
        }
    }

    int og = tid & 31, pg = tid >> 5;
    int o0 = og * 4, p0 = pg * 4;
    float acc[4][4];
    #pragma unroll
    for (int i = 0; i < 4; i++)
        #pragma unroll
        for (int j = 0; j < 4; j++) acc[i][j] = 0.f;

    for (int cc = 0; cc < 256; cc += 32) {
        __syncthreads();
        for (int idx = tid; idx < 4096; idx += 256)
            As[idx] = g_At[(size_t)(cc + (idx >> 7)) * 128 + (idx & 127)];
        __syncthreads();
        #pragma unroll
        for (int c = 0; c < 32; c++) {
            float4 w4 = *(const float4*)(As + c * 128 + o0);
            float4 v4 = *(const float4*)(xs + (cc + c) * 32 + p0);
            acc[0][0] += w4.x * v4.x; acc[0][1] += w4.x * v4.y;
            acc[0][2] += w4.x * v4.z; acc[0][3] += w4.x * v4.w;
            acc[1][0] += w4.y * v4.x; acc[1][1] += w4.y * v4.y;
            acc[1][2] += w4.y * v4.z; acc[1][3] += w4.y * v4.w;
            acc[2][0] += w4.z * v4.x; acc[2][1] += w4.z * v4.y;
            acc[2][2] += w4.z * v4.z; acc[2][3] += w4.z * v4.w;
            acc[3][0] += w4.w * v4.x; acc[3][1] += w4.w * v4.y;
            acc[3][2] += w4.w * v4.z; acc[3][3] += w4.w * v4.w;
        }
    }

    #pragma unroll
    for (int i = 0; i < 4; i++) {
        int o = o0 + i;
        float s1 = g_s1[o], s2 = g_s2[o];
        if (o < 64) {
            float* dst = g_q48 + ((size_t)b * 64 + o) * HW + hw0;
            #pragma unroll
            for (int j = 0; j < 4; j++) {
                int p = p0 + j;
                dst[p] = srs[p] * (acc[i][j] - smu[p] * s1) + s2;
            }
        } else {
            int o2 = o - 64, g = o2 >> 5, c = o2 & 31;
            float* dst = g_kT + ((size_t)(b * 2 + g) * HW + hw0) * 32 + c;
            #pragma unroll
            for (int j = 0; j < 4; j++) {
                int p = p0 + j;
                dst[p * 32] = srs[p] * (acc[i][j] - smu[p] * s1) + s2;
            }
        }
    }
}

// ---------------- 4. bilinear resize q 48->96, 4 channels/thread ---------
__global__ void k_resize() {   // grid 1152, block 256
    int idx = blockIdx.x * 256 + threadIdx.x;   // < 32*9216
    int p = idx % N1, bc = idx / N1;            // bc in 0..31
    int y = p / OHH, xo = p % OHH;
    float ys = y * SIN;  int y0 = min((int)ys, 46); float wy = ys - (float)y0;
    float xs = xo * SIN; int x0 = min((int)xs, 46); float wx = xs - (float)x0;
    int off = y0 * 48 + x0;
    float wa = (1.f - wy) * (1.f - wx), wb = (1.f - wy) * wx;
    float wc = wy * (1.f - wx),         wd = wy * wx;
    #pragma unroll
    for (int j = 0; j < 4; j++) {
        const float* bp = g_q48 + (size_t)(bc + j * 32) * HW + off;
        g_qup[idx + (size_t)(j * 32) * N1] =
            bp[0] * wa + bp[1] * wb + bp[48] * wc + bp[49] * wd;
    }
}

// ---------------- 5. dwconv3x3 + LN(32) + GELU, 4-way channel split ------
// 256 threads = 64 px x 4 quarters (8 ch each); grid (144, 4)
__global__ void __launch_bounds__(256) k_off1(const float* __restrict__ dww,
                                              const float* __restrict__ og,
                                              const float* __restrict__ ob) {
    __shared__ float ws[288], sg[32], sb[32];
    __shared__ float ps[4][64], pq[4][64];
    int tid = threadIdx.x;
    for (int i = tid; i < 288; i += 256) ws[i] = dww[i];
    if (tid < 32) { sg[tid] = og[tid]; sb[tid] = ob[tid]; }
    __syncthreads();
    int bg = blockIdx.y, b = bg >> 1, g = bg & 1;
    int pl = tid & 63, qt = tid >> 6;
    int p = blockIdx.x * 64 + pl;
    int y = p / OHH, xo = p % OHH;
    int offk[9]; float inbk[9];
    {
        int k = 0;
        #pragma unroll
        for (int dy = -1; dy <= 1; dy++)
            #pragma unroll
            for (int dx = -1; dx <= 1; dx++) {
                bool v = ((unsigned)(y + dy) < 96u) && ((unsigned)(xo + dx) < 96u);
                inbk[k] = v ? 1.f : 0.f;
                offk[k] = v ? (dy * OHH + dx) : 0;
                k++;
            }
    }
    int c0 = qt * 8;
    const float* qb = g_qup + ((size_t)b * 64 + g * 32 + c0) * N1 + p;
    float tc[8];
    float s = 0.f, q = 0.f;
    #pragma unroll
    for (int c = 0; c < 8; c++) {
        const float* pline = qb + (size_t)c * N1;
        const float* wc = ws + (c0 + c) * 9;
        float a = 0.f;
        #pragma unroll
        for (int k = 0; k < 9; k++)
            a = fmaf(wc[k] * inbk[k], pline[offk[k]], a);
        tc[c] = a; s += a; q += a * a;
    }
    ps[qt][pl] = s; pq[qt][pl] = q;
    __syncthreads();
    float S = ps[0][pl] + ps[1][pl] + ps[2][pl] + ps[3][pl];
    float Q = pq[0][pl] + pq[1][pl] + pq[2][pl] + pq[3][pl];
    float mu = S * (1.f / 32.f);
    float rstd = rsqrtf(Q * (1.f / 32.f) - mu * mu + 1e-5f);
    float4* dst = (float4*)(g_t + ((size_t)bg * N1 + p) * 32) + qt * 2;
    #pragma unroll
    for (int c4 = 0; c4 < 2; c4++) {
        float4 o4;
        float* po = (float*)&o4;
        #pragma unroll
        for (int j = 0; j < 4; j++) {
            int c = c4 * 4 + j;
            float tn = (tc[c] - mu) * rstd * sg[c0 + c] + sb[c0 + c];
            po[j] = 0.5f * tn * (1.f + erff(tn * 0.70710678118654752f));
        }
        dst[c4] = o4;
    }
}

// ---------------- 6. conv3x3 32->18 + bias + tanh -> corner tables -------
// 256 threads = 128 pixels x 2 channel-halves; grid (72, 4)
__global__ void __launch_bounds__(256) k_off2(const float* __restrict__ ow,
                                              const float* __restrict__ obias) {
    __shared__ float ws[5184];       // re-laid [k][o][c]
    __shared__ float bs[18];
    __shared__ float part[18][128];  // half-1 partials
    int tid = threadIdx.x;
    for (int i = tid; i < 5184; i += 256) {
        int o = i / 288, r = i - o * 288;
        int c = r / 9, k = r - c * 9;
        ws[(k * 18 + o) * 32 + c] = ow[i];
    }
    if (tid < 18) bs[tid] = obias[tid];
    __syncthreads();
    int bg = blockIdx.y;
    int pl = tid & 127, half = tid >> 7;
    int p = blockIdx.x * 128 + pl;
    int y = p / OHH, xo = p % OHH;
    int offk[9]; bool inbk[9];
    {
        int k = 0;
        #pragma unroll
        for (int dy = -1; dy <= 1; dy++)
            #pragma unroll
            for (int dx = -1; dx <= 1; dx++) {
                bool v = ((unsigned)(y + dy) < 96u) && ((unsigned)(xo + dx) < 96u);
                inbk[k] = v;
                offk[k] = v ? (dy * OHH + dx) : 0;
                k++;
            }
    }
    const float* tb = g_t + (size_t)bg * N1 * 32;
    float acc[18];
    #pragma unroll
    for (int o = 0; o < 18; o++) acc[o] = 0.f;
    for (int k = 0; k < 9; k++) {
        if (!inbk[k]) continue;
        const float4* vp = (const float4*)(tb + (size_t)(p + offk[k]) * 32) + half * 4;
        float4 v[4];
        #pragma unroll
        for (int j = 0; j < 4; j++) v[j] = vp[j];
        #pragma unroll
        for (int o = 0; o < 18; o++) {
            const float4* wp = (const float4*)(ws + (k * 18 + o) * 32) + half * 4;
            float a = acc[o];
            #pragma unroll
            for (int j = 0; j < 4; j++) {
                float4 w4 = wp[j];
                a += w4.x * v[j].x + w4.y * v[j].y + w4.z * v[j].z + w4.w * v[j].w;
            }
            acc[o] = a;
        }
    }
    if (half == 1) {
        #pragma unroll
        for (int o = 0; o < 18; o++) part[o][pl] = acc[o];
    }
    __syncthreads();
    if (half == 0) {
        #pragma unroll
        for (int o = 0; o < 18; o++) acc[o] += part[o][pl];
        #pragma unroll
        for (int kk = 0; kk < 9; kk++) {
            int ky = kk / 3, kx = kk % 3;
            float ey = tanhf(acc[2 * kk]     + bs[2 * kk])     * RFf + (float)(ky - 1) + (float)y;
            float ex = tanhf(acc[2 * kk + 1] + bs[2 * kk + 1]) * RFf + (float)(kx - 1) + (float)xo;
            Corner cr = mk_corner(ey * SIN, ex * SIN);
            size_t o = (size_t)(bg * NK + kk) * N1 + p;
            g_ci[o] = make_int4(cr.i00 * 32, cr.i01 * 32, cr.i10 * 32, cr.i11 * 32);
            g_cw[o] = make_float4(cr.w00, cr.w01, cr.w10, cr.w11);
        }
    }
}

// ---------------- 7. fused deformable gather + attention -----------------
// smem-staged q / corner tables; fp16 V; ALL gathers (K+V) hoisted above softmax
__global__ void __launch_bounds__(256) k_attn(const float* __restrict__ rpb,
                                              float* __restrict__ out) {
    __shared__ float  rp[288];
    __shared__ float  qs[32 * 33];    // [c][p]
    __shared__ int4   cis[9][32];
    __shared__ float4 cws[9][32];
    __shared__ float  obuf[32 * 129];
    int tid = threadIdx.x;
    int b = blockIdx.z, h = blockIdx.y, bg = b * 2 + h;
    int tr = blockIdx.x / 3, tc3 = blockIdx.x % 3;
    int gy0 = tr * 4, gx0 = tc3 * 32;     // 4-row x 32-col output tile

    for (int i = tid; i < 288; i += 256) rp[i] = rpb[h * 288 + i];

    int lane = tid & 31, w = tid >> 5;
    const float* kb = g_kT + (size_t)bg * HW * 32;
    const uint2* vb = (const uint2*)(g_vTh + (size_t)bg * HW * 128);  // 4 halves/lane
    const float* qbase = g_qup + (size_t)(b * 64 + h * 32) * N1;
    const int4*   cib = g_ci + (size_t)bg * NK * N1;
    const float4* cwb = g_cw + (size_t)bg * NK * N1;

    for (int rr = 0; rr < 4; rr++) {
        int prow = (gy0 + rr) * 96 + gx0;
        __syncthreads();
        for (int idx = tid; idx < 1024; idx += 256) {
            int c = idx >> 5, p = idx & 31;
            qs[c * 33 + p] = qbase[(size_t)c * N1 + prow + p] * SCLQ;
        }
        for (int idx = tid; idx < 288; idx += 256) {
            int kk = idx >> 5, p = idx & 31;
            cis[kk][p] = cib[(size_t)kk * N1 + prow + p];
            cws[kk][p] = cwb[(size_t)kk * N1 + prow + p];
        }
        __syncthreads();

        #pragma unroll
        for (int j = 0; j < 4; j++) {
            int pl = j * 8 + w;
            float qv = qs[lane * 33 + pl];

            // Phase 1: ALL gathers up front (36 K-LDG + 36 V-LDG, max MLP).
            // Corner-weighted V pre-accumulation: vtap[kk] = sum_c w_c * V_c
            // (valid because corner weights don't depend on the softmax).
            float  kvv[9];
            float4 vtap[9];
            #pragma unroll
            for (int kk = 0; kk < 9; kk++) {
                int4   pi = cis[kk][pl];
                float4 pw = cws[kk][pl];
                kvv[kk] = pw.x * kb[pi.x + lane]
                        + pw.y * kb[pi.y + lane]
                        + pw.z * kb[pi.z + lane]
                        + pw.w * kb[pi.w + lane];
                uint2 r0 = vb[pi.x + lane];
                uint2 r1 = vb[pi.y + lane];
                uint2 r2 = vb[pi.z + lane];
                uint2 r3 = vb[pi.w + lane];
                float2 f0a = __half22float2(*(const __half2*)&r0.x);
                float2 f0b = __half22float2(*(const __half2*)&r0.y);
                float2 f1a = __half22float2(*(const __half2*)&r1.x);
                float2 f1b = __half22float2(*(const __half2*)&r1.y);
                float2 f2a = __half22float2(*(const __half2*)&r2.x);
                float2 f2b = __half22float2(*(const __half2*)&r2.y);
                float2 f3a = __half22float2(*(const __half2*)&r3.x);
                float2 f3b = __half22float2(*(const __half2*)&r3.y);
                float4 vt;
                vt.x = pw.x * f0a.x + pw.y * f1a.x + pw.z * f2a.x + pw.w * f3a.x;
                vt.y = pw.x * f0a.y + pw.y * f1a.y + pw.z * f2a.y + pw.w * f3a.y;
                vt.z = pw.x * f0b.x + pw.y * f1b.x + pw.z * f2b.x + pw.w * f3b.x;
                vt.w = pw.x * f0b.y + pw.y * f1b.y + pw.z * f2b.y + pw.w * f3b.y;
                vtap[kk] = vt;
            }
            // Phase 2: logits + softmax (shfl chains overlap V-load latency)
            float lg[9];
            #pragma unroll
            for (int kk = 0; kk < 9; kk++) {
                float pt = qv * (kvv[kk] + rp[kk * 32 + lane]);
                #pragma unroll
                for (int o = 16; o; o >>= 1) pt += __shfl_xor_sync(0xffffffffu, pt, o);
                lg[kk] = pt;
            }
            float m = lg[0];
            #pragma unroll
            for (int kk = 1; kk < 9; kk++) m = fmaxf(m, lg[kk]);
            float s = 0.f;
            #pragma unroll
            for (int kk = 0; kk < 9; kk++) { lg[kk] = __expf(lg[kk] - m); s += lg[kk]; }
            float inv = 1.f / s;

            // Phase 3: pure-register weighted accumulation (no loads)
            float4 acc = make_float4(0.f, 0.f, 0.f, 0.f);
            #pragma unroll
            for (int kk = 0; kk < 9; kk++) {
                float a = lg[kk] * inv;
                acc.x += a * vtap[kk].x;
                acc.y += a * vtap[kk].y;
                acc.z += a * vtap[kk].z;
                acc.w += a * vtap[kk].w;
            }
            float* o4 = obuf + pl * 129 + lane * 4;
            o4[0] = acc.x; o4[1] = acc.y; o4[2] = acc.z; o4[3] = acc.w;
        }
        __syncthreads();
        float* ob = out + ((size_t)(b * 256 + h * 128)) * N1 + prow;
        for (int idx = tid; idx < 4096; idx += 256) {
            int c2 = idx >> 5, cc = idx & 31;
            ob[(size_t)c2 * N1 + cc] = obuf[cc * 129 + c2];
        }
    }
}

// ---------------- launch --------------------------------------------------
extern "C" void kernel_launch(void* const* d_in, const int* in_sizes, int n_in,
                              void* d_out, int out_size) {
    const float* x    = (const float*)d_in[0];
    const float* ln_g = (const float*)d_in[1];
    const float* ln_b = (const float*)d_in[2];
    const float* Wq   = (const float*)d_in[3];
    const float* Wk   = (const float*)d_in[4];
    const float* dww  = (const float*)d_in[5];
    const float* olg  = (const float*)d_in[6];
    const float* olb  = (const float*)d_in[7];
    const float* ow   = (const float*)d_in[8];
    const float* obb  = (const float*)d_in[9];
    const float* rpb  = (const float*)d_in[10];
    float* out = (float*)d_out;

    k_prep  <<<128, 256>>>(Wq, Wk, ln_g, ln_b);
    k_vt    <<<dim3(72, 4, 4), dim3(32, 8)>>>(x);
    k_proj  <<<144, 256>>>(x);
    k_resize<<<1152, 256>>>();
    k_off1  <<<dim3(144, 4), 256>>>(dww, olg, olb);
    k_off2  <<<dim3(72, 4), 256>>>(ow, obb);
    k_attn  <<<dim3(72, 2, 2), 256>>>(rpb, out);
}

// round 14
// speedup vs baseline: 1.5125x; 1.5125x over previous
#include <cuda_runtime.h>
#include <cuda_fp16.h>
#include <math.h>

// Problem constants
#define BB   2
#define CC   256
#define HH   48
#define WWI  48
#define HW   2304      // 48*48
#define HID  64
#define OHH  96
#define N1   9216      // 96*96
#define NK   9
#define RFf  11.0f
#define SCLQ 0.17677669529663687f   // 32^-0.5
#define SIN  0.49473684210526314f   // 47/95  (align_corners scale)

// ---------------- scratch (device globals; no allocation) ----------------
__device__ float  g_At[256 * 128];      // fused [Wq;Wk]*ln_g, TRANSPOSED [c][o]
__device__ float  g_s1[128];
__device__ float  g_s2[128];
__device__ float  g_q48[BB * 64 * HW];  // NCHW q at 48x48
__device__ float  g_kT[4 * HW * 32];    // [bg][hw][32]  NHWC per group, fp32
__device__ __half g_vTh[4 * HW * 128];  // [bg][hw][128] NHWC per group, fp16
__device__ float  g_qup[BB * 64 * N1];  // NCHW q at 96x96
__device__ float  g_t[4 * N1 * 32];     // offset-net hidden, NHWC [bg][p][c]
__device__ int4   g_ci[4 * NK * N1];    // corner indices (premult x32)
__device__ float4 g_cw[4 * NK * N1];    // corner bilinear weights

// ---------------- bilinear corner helper (grid_sample, zeros pad) --------
struct Corner { int i00, i01, i10, i11; float w00, w01, w10, w11; };
__device__ __forceinline__ Corner mk_corner(float iy, float ix) {
    Corner r;
    float yf = floorf(iy), xf = floorf(ix);
    float wy = iy - yf, wx = ix - xf;
    int y0 = (int)yf, x0 = (int)xf;
    float vy0 = (y0 >= 0 && y0 < 48) ? 1.f : 0.f;
    float vy1 = (y0 >= -1 && y0 < 47) ? 1.f : 0.f;
    float vx0 = (x0 >= 0 && x0 < 48) ? 1.f : 0.f;
    float vx1 = (x0 >= -1 && x0 < 47) ? 1.f : 0.f;
    int yc0 = min(max(y0, 0), 47),     yc1 = min(max(y0 + 1, 0), 47);
    int xc0 = min(max(x0, 0), 47),     xc1 = min(max(x0 + 1, 0), 47);
    r.i00 = yc0 * 48 + xc0; r.i01 = yc0 * 48 + xc1;
    r.i10 = yc1 * 48 + xc0; r.i11 = yc1 * 48 + xc1;
    r.w00 = (1.f - wy) * (1.f - wx) * vy0 * vx0;
    r.w01 = (1.f - wy) * wx        * vy0 * vx1;
    r.w10 = wy        * (1.f - wx) * vy1 * vx0;
    r.w11 = wy        * wx         * vy1 * vx1;
    return r;
}

// ---------------- 1. fold LN affine into projection weights --------------
__global__ void k_prep(const float* __restrict__ Wq, const float* __restrict__ Wk,
                       const float* __restrict__ lg, const float* __restrict__ lb) {
    int o = blockIdx.x;          // 0..127
    int c = threadIdx.x;         // 0..255
    const float* Wrow = (o < 64) ? (Wq + o * 256) : (Wk + (o - 64) * 256);
    float w = Wrow[c];
    float a = w * lg[c];
    g_At[c * 128 + o] = a;       // transposed store
    __shared__ float s1s[256], s2s[256];
    s1s[c] = a; s2s[c] = w * lb[c];
    __syncthreads();
    for (int st = 128; st; st >>= 1) {
        if (c < st) { s1s[c] += s1s[c + st]; s2s[c] += s2s[c + st]; }
        __syncthreads();
    }
    if (c == 0) { g_s1[o] = s1s[0]; g_s2[o] = s2s[0]; }
}

// ---------------- 2. V transpose to NHWC per group (fp16 store) ----------
__global__ void k_vt(const float* __restrict__ x) {  // grid (72,4,4), block (32,8)
    __shared__ float tile[32][33];
    int hwt = blockIdx.x * 32, ct = blockIdx.y * 32, bg = blockIdx.z;
    int b = bg >> 1, g = bg & 1;
    const float* src = x + ((size_t)b * 256 + g * 128 + ct) * HW;
    int tx = threadIdx.x, ty = threadIdx.y;
    #pragma unroll
    for (int j = 0; j < 4; j++) {
        int c = ty + j * 8;
        tile[c][tx] = src[(size_t)c * HW + hwt + tx];
    }
    __syncthreads();
    __half* dst = g_vTh + ((size_t)bg * HW + hwt) * 128 + ct;
    #pragma unroll
    for (int j = 0; j < 4; j++) {
        int r = ty + j * 8;
        dst[(size_t)r * 128 + tx] = __float2half(tile[tx][r]);
    }
}

// ---------------- 3. fused LN-stats + LN + Q/K projection (smem GEMM) ----
__global__ void __launch_bounds__(256) k_proj(const float* __restrict__ x) {
    __shared__ float xs[256 * 32];    // 32KB  [c][p]
    __shared__ float As[32 * 128];    // 16KB  weight chunk [c][o]
    __shared__ float smu[32], srs[32];
    __shared__ float rs_[8][32], rq_[8][32];
    int tid = threadIdx.x;
    int px0 = blockIdx.x * 32;
    int b = px0 / HW, hw0 = px0 - b * HW;
    const float* xb = x + (size_t)b * CC * HW;
    for (int idx = tid; idx < 8192; idx += 256) {
        int c = idx >> 5, p = idx & 31;
        xs[idx] = xb[(size_t)c * HW + hw0 + p];
    }
    __syncthreads();
    {
        int p = tid & 31, cg = tid >> 5;
        float s = 0.f, q = 0.f;
        #pragma unroll 8
        for (int i = 0; i < 32; i++) {
            float v = xs[(cg * 32 + i) * 32 + p];
            s += v; q += v * v;
        }
        rs_[cg][p] = s; rq_[cg][p] = q;
        __syncthreads();
        if (tid < 32) {
            float S = 0.f, Q = 0.f;
            #pragma unroll
            for (int g2 = 0; g2 < 8; g2++) { S += rs_[g2][tid]; Q += rq_[g2][tid]; }
            float mu = S * (1.f / 256.f);
            smu[tid] = mu;
            srs[tid] = rsqrtf(Q * (1.f / 256.f) - mu * mu + 1e-5f);
        }
    }

    int og = tid & 31, pg = tid >> 5;
    int o0 = og * 4, p0 = pg * 4;
    float acc[4][4];
    #pragma unroll
    for (int i = 0; i < 4; i++)
        #pragma unroll
        for (int j = 0; j < 4; j++) acc[i][j] = 0.f;

    for (int cc = 0; cc < 256; cc += 32) {
        __syncthreads();
        for (int idx = tid; idx < 4096; idx += 256)
            As[idx] = g_At[(size_t)(cc + (idx >> 7)) * 128 + (idx & 127)];
        __syncthreads();
        #pragma unroll
        for (int c = 0; c < 32; c++) {
            float4 w4 = *(const float4*)(As + c * 128 + o0);
            float4 v4 = *(const float4*)(xs + (cc + c) * 32 + p0);
            acc[0][0] += w4.x * v4.x; acc[0][1] += w4.x * v4.y;
            acc[0][2] += w4.x * v4.z; acc[0][3] += w4.x * v4.w;
            acc[1][0] += w4.y * v4.x; acc[1][1] += w4.y * v4.y;
            acc[1][2] += w4.y * v4.z; acc[1][3] += w4.y * v4.w;
            acc[2][0] += w4.z * v4.x; acc[2][1] += w4.z * v4.y;
            acc[2][2] += w4.z * v4.z; acc[2][3] += w4.z * v4.w;
            acc[3][0] += w4.w * v4.x; acc[3][1] += w4.w * v4.y;
            acc[3][2] += w4.w * v4.z; acc[3][3] += w4.w * v4.w;
        }
    }

    #pragma unroll
    for (int i = 0; i < 4; i++) {
        int o = o0 + i;
        float s1 = g_s1[o], s2 = g_s2[o];
        if (o < 64) {
            float* dst = g_q48 + ((size_t)b * 64 + o) * HW + hw0;
            #pragma unroll
            for (int j = 0; j < 4; j++) {
                int p = p0 + j;
                dst[p] = srs[p] * (acc[i][j] - smu[p] * s1) + s2;
            }
        } else {
            int o2 = o - 64, g = o2 >> 5, c = o2 & 31;
            float* dst = g_kT + ((size_t)(b * 2 + g) * HW + hw0) * 32 + c;
            #pragma unroll
            for (int j = 0; j < 4; j++) {
                int p = p0 + j;
                dst[p * 32] = srs[p] * (acc[i][j] - smu[p] * s1) + s2;
            }
        }
    }
}

// ---------------- 4. bilinear resize q 48->96, 4 channels/thread ---------
__global__ void k_resize() {   // grid 1152, block 256
    int idx = blockIdx.x * 256 + threadIdx.x;   // < 32*9216
    int p = idx % N1, bc = idx / N1;            // bc in 0..31
    int y = p / OHH, xo = p % OHH;
    float ys = y * SIN;  int y0 = min((int)ys, 46); float wy = ys - (float)y0;
    float xs = xo * SIN; int x0 = min((int)xs, 46); float wx = xs - (float)x0;
    int off = y0 * 48 + x0;
    float wa = (1.f - wy) * (1.f - wx), wb = (1.f - wy) * wx;
    float wc = wy * (1.f - wx),         wd = wy * wx;
    #pragma unroll
    for (int j = 0; j < 4; j++) {
        const float* bp = g_q48 + (size_t)(bc + j * 32) * HW + off;
        g_qup[idx + (size_t)(j * 32) * N1] =
            bp[0] * wa + bp[1] * wb + bp[48] * wc + bp[49] * wd;
    }
}

// ---------------- 5. dwconv3x3 + LN(32) + GELU, 4-way channel split ------
// 256 threads = 64 px x 4 quarters (8 ch each); grid (144, 4)
__global__ void __launch_bounds__(256) k_off1(const float* __restrict__ dww,
                                              const float* __restrict__ og,
                                              const float* __restrict__ ob) {
    __shared__ float ws[288], sg[32], sb[32];
    __shared__ float ps[4][64], pq[4][64];
    int tid = threadIdx.x;
    for (int i = tid; i < 288; i += 256) ws[i] = dww[i];
    if (tid < 32) { sg[tid] = og[tid]; sb[tid] = ob[tid]; }
    __syncthreads();
    int bg = blockIdx.y, b = bg >> 1, g = bg & 1;
    int pl = tid & 63, qt = tid >> 6;
    int p = blockIdx.x * 64 + pl;
    int y = p / OHH, xo = p % OHH;
    int offk[9]; float inbk[9];
    {
        int k = 0;
        #pragma unroll
        for (int dy = -1; dy <= 1; dy++)
            #pragma unroll
            for (int dx = -1; dx <= 1; dx++) {
                bool v = ((unsigned)(y + dy) < 96u) && ((unsigned)(xo + dx) < 96u);
                inbk[k] = v ? 1.f : 0.f;
                offk[k] = v ? (dy * OHH + dx) : 0;
                k++;
            }
    }
    int c0 = qt * 8;
    const float* qb = g_qup + ((size_t)b * 64 + g * 32 + c0) * N1 + p;
    float tc[8];
    float s = 0.f, q = 0.f;
    #pragma unroll
    for (int c = 0; c < 8; c++) {
        const float* pline = qb + (size_t)c * N1;
        const float* wc = ws + (c0 + c) * 9;
        float a = 0.f;
        #pragma unroll
        for (int k = 0; k < 9; k++)
            a = fmaf(wc[k] * inbk[k], pline[offk[k]], a);
        tc[c] = a; s += a; q += a * a;
    }
    ps[qt][pl] = s; pq[qt][pl] = q;
    __syncthreads();
    float S = ps[0][pl] + ps[1][pl] + ps[2][pl] + ps[3][pl];
    float Q = pq[0][pl] + pq[1][pl] + pq[2][pl] + pq[3][pl];
    float mu = S * (1.f / 32.f);
    float rstd = rsqrtf(Q * (1.f / 32.f) - mu * mu + 1e-5f);
    float4* dst = (float4*)(g_t + ((size_t)bg * N1 + p) * 32) + qt * 2;
    #pragma unroll
    for (int c4 = 0; c4 < 2; c4++) {
        float4 o4;
        float* po = (float*)&o4;
        #pragma unroll
        for (int j = 0; j < 4; j++) {
            int c = c4 * 4 + j;
            float tn = (tc[c] - mu) * rstd * sg[c0 + c] + sb[c0 + c];
            po[j] = 0.5f * tn * (1.f + erff(tn * 0.70710678118654752f));
        }
        dst[c4] = o4;
    }
}

// ---------------- 6. conv3x3 32->18 + bias + tanh -> corner tables -------
// 256 threads = 128 pixels x 2 channel-halves; grid (72, 4)
__global__ void __launch_bounds__(256) k_off2(const float* __restrict__ ow,
                                              const float* __restrict__ obias) {
    __shared__ float ws[5184];       // re-laid [k][o][c]
    __shared__ float bs[18];
    __shared__ float part[18][128];  // half-1 partials
    int tid = threadIdx.x;
    for (int i = tid; i < 5184; i += 256) {
        int o = i / 288, r = i - o * 288;
        int c = r / 9, k = r - c * 9;
        ws[(k * 18 + o) * 32 + c] = ow[i];
    }
    if (tid < 18) bs[tid] = obias[tid];
    __syncthreads();
    int bg = blockIdx.y;
    int pl = tid & 127, half = tid >> 7;
    int p = blockIdx.x * 128 + pl;
    int y = p / OHH, xo = p % OHH;
    int offk[9]; bool inbk[9];
    {
        int k = 0;
        #pragma unroll
        for (int dy = -1; dy <= 1; dy++)
            #pragma unroll
            for (int dx = -1; dx <= 1; dx++) {
                bool v = ((unsigned)(y + dy) < 96u) && ((unsigned)(xo + dx) < 96u);
                inbk[k] = v;
                offk[k] = v ? (dy * OHH + dx) : 0;
                k++;
            }
    }
    const float* tb = g_t + (size_t)bg * N1 * 32;
    float acc[18];
    #pragma unroll
    for (int o = 0; o < 18; o++) acc[o] = 0.f;
    for (int k = 0; k < 9; k++) {
        if (!inbk[k]) continue;
        const float4* vp = (const float4*)(tb + (size_t)(p + offk[k]) * 32) + half * 4;
        float4 v[4];
        #pragma unroll
        for (int j = 0; j < 4; j++) v[j] = vp[j];
        #pragma unroll
        for (int o = 0; o < 18; o++) {
            const float4* wp = (const float4*)(ws + (k * 18 + o) * 32) + half * 4;
            float a = acc[o];
            #pragma unroll
            for (int j = 0; j < 4; j++) {
                float4 w4 = wp[j];
                a += w4.x * v[j].x + w4.y * v[j].y + w4.z * v[j].z + w4.w * v[j].w;
            }
            acc[o] = a;
        }
    }
    if (half == 1) {
        #pragma unroll
        for (int o = 0; o < 18; o++) part[o][pl] = acc[o];
    }
    __syncthreads();
    if (half == 0) {
        #pragma unroll
        for (int o = 0; o < 18; o++) acc[o] += part[o][pl];
        #pragma unroll
        for (int kk = 0; kk < 9; kk++) {
            int ky = kk / 3, kx = kk % 3;
            float ey = tanhf(acc[2 * kk]     + bs[2 * kk])     * RFf + (float)(ky - 1) + (float)y;
            float ex = tanhf(acc[2 * kk + 1] + bs[2 * kk + 1]) * RFf + (float)(kx - 1) + (float)xo;
            Corner cr = mk_corner(ey * SIN, ex * SIN);
            size_t o = (size_t)(bg * NK + kk) * N1 + p;
            g_ci[o] = make_int4(cr.i00 * 32, cr.i01 * 32, cr.i10 * 32, cr.i11 * 32);
            g_cw[o] = make_float4(cr.w00, cr.w01, cr.w10, cr.w11);
        }
    }
}

// ---------------- 7. fused deformable gather + attention -----------------
// smem-staged q / corner tables; fp16 V; K-gather decoupled from reduce
__global__ void __launch_bounds__(256) k_attn(const float* __restrict__ rpb,
                                              float* __restrict__ out) {
    __shared__ float  rp[288];
    __shared__ float  qs[32 * 33];    // [c][p]
    __shared__ int4   cis[9][32];
    __shared__ float4 cws[9][32];
    __shared__ float  obuf[32 * 129];
    int tid = threadIdx.x;
    int b = blockIdx.z, h = blockIdx.y, bg = b * 2 + h;
    int tr = blockIdx.x / 3, tc3 = blockIdx.x % 3;
    int gy0 = tr * 4, gx0 = tc3 * 32;     // 4-row x 32-col output tile

    for (int i = tid; i < 288; i += 256) rp[i] = rpb[h * 288 + i];

    int lane = tid & 31, w = tid >> 5;
    const float* kb = g_kT + (size_t)bg * HW * 32;
    const uint2* vb = (const uint2*)(g_vTh + (size_t)bg * HW * 128);  // 4 halves/lane
    const float* qbase = g_qup + (size_t)(b * 64 + h * 32) * N1;
    const int4*   cib = g_ci + (size_t)bg * NK * N1;
    const float4* cwb = g_cw + (size_t)bg * NK * N1;

    for (int rr = 0; rr < 4; rr++) {
        int prow = (gy0 + rr) * 96 + gx0;
        __syncthreads();
        for (int idx = tid; idx < 1024; idx += 256) {
            int c = idx >> 5, p = idx & 31;
            qs[c * 33 + p] = qbase[(size_t)c * N1 + prow + p] * SCLQ;
        }
        for (int idx = tid; idx < 288; idx += 256) {
            int kk = idx >> 5, p = idx & 31;
            cis[kk][p] = cib[(size_t)kk * N1 + prow + p];
            cws[kk][p] = cwb[(size_t)kk * N1 + prow + p];
        }
        __syncthreads();

        #pragma unroll
        for (int j = 0; j < 4; j++) {
            int pl = j * 8 + w;
            float qv = qs[lane * 33 + pl];

            // Phase 1: batched K gather (36 independent LDGs before any reduce)
            float kvv[9];
            #pragma unroll
            for (int kk = 0; kk < 9; kk++) {
                int4   pi = cis[kk][pl];
                float4 pw = cws[kk][pl];
                kvv[kk] = pw.x * kb[pi.x + lane]
                        + pw.y * kb[pi.y + lane]
                        + pw.z * kb[pi.z + lane]
                        + pw.w * kb[pi.w + lane];
            }
            // Phase 2: reduce chains (shfl latency overlapped across taps)
            float lg[9];
            #pragma unroll
            for (int kk = 0; kk < 9; kk++) {
                float pt = qv * (kvv[kk] + rp[kk * 32 + lane]);
                #pragma unroll
                for (int o = 16; o; o >>= 1) pt += __shfl_xor_sync(0xffffffffu, pt, o);
                lg[kk] = pt;
            }
            float m = lg[0];
            #pragma unroll
            for (int kk = 1; kk < 9; kk++) m = fmaxf(m, lg[kk]);
            float s = 0.f;
            #pragma unroll
            for (int kk = 0; kk < 9; kk++) { lg[kk] = __expf(lg[kk] - m); s += lg[kk]; }
            float inv = 1.f / s;

            float4 acc = make_float4(0.f, 0.f, 0.f, 0.f);
            #pragma unroll
            for (int kk = 0; kk < 9; kk++) {
                int4   pi = cis[kk][pl];
                float4 pw = cws[kk][pl];
                float a = lg[kk] * inv;
                float a00 = a * pw.x, a01 = a * pw.y, a10 = a * pw.z, a11 = a * pw.w;
                uint2 r0 = vb[pi.x + lane];
                uint2 r1 = vb[pi.y + lane];
                uint2 r2 = vb[pi.z + lane];
                uint2 r3 = vb[pi.w + lane];
                float2 f0a = __half22float2(*(const __half2*)&r0.x);
                float2 f0b = __half22float2(*(const __half2*)&r0.y);
                float2 f1a = __half22float2(*(const __half2*)&r1.x);
                float2 f1b = __half22float2(*(const __half2*)&r1.y);
                float2 f2a = __half22float2(*(const __half2*)&r2.x);
                float2 f2b = __half22float2(*(const __half2*)&r2.y);
                float2 f3a = __half22float2(*(const __half2*)&r3.x);
                float2 f3b = __half22float2(*(const __half2*)&r3.y);
                acc.x += a00 * f0a.x + a01 * f1a.x + a10 * f2a.x + a11 * f3a.x;
                acc.y += a00 * f0a.y + a01 * f1a.y + a10 * f2a.y + a11 * f3a.y;
                acc.z += a00 * f0b.x + a01 * f1b.x + a10 * f2b.x + a11 * f3b.x;
                acc.w += a00 * f0b.y + a01 * f1b.y + a10 * f2b.y + a11 * f3b.y;
            }
            float* o4 = obuf + pl * 129 + lane * 4;
            o4[0] = acc.x; o4[1] = acc.y; o4[2] = acc.z; o4[3] = acc.w;
        }
        __syncthreads();
        float* ob = out + ((size_t)(b * 256 + h * 128)) * N1 + prow;
        for (int idx = tid; idx < 4096; idx += 256) {
            int c2 = idx >> 5, cc = idx & 31;
            ob[(size_t)c2 * N1 + cc] = obuf[cc * 129 + c2];
        }
    }
}

// ---------------- launch --------------------------------------------------
extern "C" void kernel_launch(void* const* d_in, const int* in_sizes, int n_in,
                              void* d_out, int out_size) {
    const float* x    = (const float*)d_in[0];
    const float* ln_g = (const float*)d_in[1];
    const float* ln_b = (const float*)d_in[2];
    const float* Wq   = (const float*)d_in[3];
    const float* Wk   = (const float*)d_in[4];
    const float* dww  = (const float*)d_in[5];
    const float* olg  = (const float*)d_in[6];
    const float* olb  = (const float*)d_in[7];
    const float* ow   = (const float*)d_in[8];
    const float* obb  = (const float*)d_in[9];
    const float* rpb  = (const float*)d_in[10];
    float* out = (float*)d_out;

    k_prep  <<<128, 256>>>(Wq, Wk, ln_g, ln_b);
    k_vt    <<<dim3(72, 4, 4), dim3(32, 8)>>>(x);
    k_proj  <<<144, 256>>>(x);
    k_resize<<<1152, 256>>>();
    k_off1  <<<dim3(144, 4), 256>>>(dww, olg, olb);
    k_off2  <<<dim3(72, 4), 256>>>(ow, obb);
    k_attn  <<<dim3(72, 2, 2), 256>>>(rpb, out);
}

// round 15
// speedup vs baseline: 1.5343x; 1.0144x over previous
#include <cuda_runtime.h>
#include <cuda_fp16.h>
#include <math.h>

// Problem constants
#define BB   2
#define CC   256
#define HH   48
#define WWI  48
#define HW   2304      // 48*48
#define HID  64
#define OHH  96
#define N1   9216      // 96*96
#define NK   9
#define RFf  11.0f
#define SCLQ 0.17677669529663687f   // 32^-0.5
#define SIN  0.49473684210526314f   // 47/95  (align_corners scale)

// ---------------- packed f32x2 helpers (sm_103a FFMA2 via PTX) -----------
__device__ __forceinline__ unsigned long long pack2(float x, float y) {
    unsigned long long r;
    asm("mov.b64 %0, {%1, %2};" : "=l"(r) : "f"(x), "f"(y));
    return r;
}
__device__ __forceinline__ float2 unpack2(unsigned long long v) {
    float2 r;
    asm("mov.b64 {%0, %1}, %2;" : "=f"(r.x), "=f"(r.y) : "l"(v));
    return r;
}
__device__ __forceinline__ void ffma2(unsigned long long& d,
                                      unsigned long long a, unsigned long long b) {
    asm("fma.rn.f32x2 %0, %1, %2, %0;" : "+l"(d) : "l"(a), "l"(b));
}

// ---------------- scratch (device globals; no allocation) ----------------
__device__ float  g_At[256 * 128];      // fused [Wq;Wk]*ln_g, TRANSPOSED [c][o]
__device__ float  g_s1[128];
__device__ float  g_s2[128];
__device__ float  g_q48[BB * 64 * HW];  // NCHW q at 48x48
__device__ float  g_kT[4 * HW * 32];    // [bg][hw][32]  NHWC per group, fp32
__device__ __half g_vTh[4 * HW * 128];  // [bg][hw][128] NHWC per group, fp16
__device__ float  g_qup[BB * 64 * N1];  // NCHW q at 96x96
__device__ float  g_t[4 * N1 * 32];     // offset-net hidden, NHWC [bg][p][c]
__device__ int4   g_ci[4 * NK * N1];    // corner indices (premult x32)
__device__ float4 g_cw[4 * NK * N1];    // corner bilinear weights

// ---------------- bilinear corner helper (grid_sample, zeros pad) --------
struct Corner { int i00, i01, i10, i11; float w00, w01, w10, w11; };
__device__ __forceinline__ Corner mk_corner(float iy, float ix) {
    Corner r;
    float yf = floorf(iy), xf = floorf(ix);
    float wy = iy - yf, wx = ix - xf;
    int y0 = (int)yf, x0 = (int)xf;
    float vy0 = (y0 >= 0 && y0 < 48) ? 1.f : 0.f;
    float vy1 = (y0 >= -1 && y0 < 47) ? 1.f : 0.f;
    float vx0 = (x0 >= 0 && x0 < 48) ? 1.f : 0.f;
    float vx1 = (x0 >= -1 && x0 < 47) ? 1.f : 0.f;
    int yc0 = min(max(y0, 0), 47),     yc1 = min(max(y0 + 1, 0), 47);
    int xc0 = min(max(x0, 0), 47),     xc1 = min(max(x0 + 1, 0), 47);
    r.i00 = yc0 * 48 + xc0; r.i01 = yc0 * 48 + xc1;
    r.i10 = yc1 * 48 + xc0; r.i11 = yc1 * 48 + xc1;
    r.w00 = (1.f - wy) * (1.f - wx) * vy0 * vx0;
    r.w01 = (1.f - wy) * wx        * vy0 * vx1;
    r.w10 = wy        * (1.f - wx) * vy1 * vx0;
    r.w11 = wy        * wx         * vy1 * vx1;
    return r;
}

// ---------------- 1. fold LN affine into projection weights --------------
__global__ void k_prep(const float* __restrict__ Wq, const float* __restrict__ Wk,
                       const float* __restrict__ lg, const float* __restrict__ lb) {
    int o = blockIdx.x;          // 0..127
    int c = threadIdx.x;         // 0..255
    const float* Wrow = (o < 64) ? (Wq + o * 256) : (Wk + (o - 64) * 256);
    float w = Wrow[c];
    float a = w * lg[c];
    g_At[c * 128 + o] = a;       // transposed store
    __shared__ float s1s[256], s2s[256];
    s1s[c] = a; s2s[c] = w * lb[c];
    __syncthreads();
    for (int st = 128; st; st >>= 1) {
        if (c < st) { s1s[c] += s1s[c + st]; s2s[c] += s2s[c + st]; }
        __syncthreads();
    }
    if (c == 0) { g_s1[o] = s1s[0]; g_s2[o] = s2s[0]; }
}

// ---------------- 2. V transpose to NHWC per group (fp16 store) ----------
__global__ void k_vt(const float* __restrict__ x) {  // grid (72,4,4), block (32,8)
    __shared__ float tile[32][33];
    int hwt = blockIdx.x * 32, ct = blockIdx.y * 32, bg = blockIdx.z;
    int b = bg >> 1, g = bg & 1;
    const float* src = x + ((size_t)b * 256 + g * 128 + ct) * HW;
    int tx = threadIdx.x, ty = threadIdx.y;
    #pragma unroll
    for (int j = 0; j < 4; j++) {
        int c = ty + j * 8;
        tile[c][tx] = src[(size_t)c * HW + hwt + tx];
    }
    __syncthreads();
    __half* dst = g_vTh + ((size_t)bg * HW + hwt) * 128 + ct;
    #pragma unroll
    for (int j = 0; j < 4; j++) {
        int r = ty + j * 8;
        dst[(size_t)r * 128 + tx] = __float2half(tile[tx][r]);
    }
}

// ---------------- 3. fused LN-stats + LN + Q/K projection (smem GEMM) ----
// inner loop uses packed f32x2 FMA over output pairs
__global__ void __launch_bounds__(256) k_proj(const float* __restrict__ x) {
    __shared__ float xs[256 * 32];    // 32KB  [c][p]
    __shared__ float As[32 * 128];    // 16KB  weight chunk [c][o]
    __shared__ float smu[32], srs[32];
    __shared__ float rs_[8][32], rq_[8][32];
    int tid = threadIdx.x;
    int px0 = blockIdx.x * 32;
    int b = px0 / HW, hw0 = px0 - b * HW;
    const float* xb = x + (size_t)b * CC * HW;
    for (int idx = tid; idx < 8192; idx += 256) {
        int c = idx >> 5, p = idx & 31;
        xs[idx] = xb[(size_t)c * HW + hw0 + p];
    }
    __syncthreads();
    {
        int p = tid & 31, cg = tid >> 5;
        float s = 0.f, q = 0.f;
        #pragma unroll 8
        for (int i = 0; i < 32; i++) {
            float v = xs[(cg * 32 + i) * 32 + p];
            s += v; q += v * v;
        }
        rs_[cg][p] = s; rq_[cg][p] = q;
        __syncthreads();
        if (tid < 32) {
            float S = 0.f, Q = 0.f;
            #pragma unroll
            for (int g2 = 0; g2 < 8; g2++) { S += rs_[g2][tid]; Q += rq_[g2][tid]; }
            float mu = S * (1.f / 256.f);
            smu[tid] = mu;
            srs[tid] = rsqrtf(Q * (1.f / 256.f) - mu * mu + 1e-5f);
        }
    }

    int og = tid & 31, pg = tid >> 5;
    int o0 = og * 4, p0 = pg * 4;
    // acc2[r][j] = packed (out o0+2r, o0+2r+1) for pixel p0+j
    unsigned long long acc2[2][4];
    #pragma unroll
    for (int r = 0; r < 2; r++)
        #pragma unroll
        for (int j = 0; j < 4; j++) acc2[r][j] = 0ull;

    for (int cc = 0; cc < 256; cc += 32) {
        __syncthreads();
        for (int idx = tid; idx < 4096; idx += 256)
            As[idx] = g_At[(size_t)(cc + (idx >> 7)) * 128 + (idx & 127)];
        __syncthreads();
        #pragma unroll
        for (int c = 0; c < 32; c++) {
            float4 w4 = *(const float4*)(As + c * 128 + o0);
            float4 v4 = *(const float4*)(xs + (cc + c) * 32 + p0);
            unsigned long long wA = pack2(w4.x, w4.y);
            unsigned long long wB = pack2(w4.z, w4.w);
            unsigned long long vx = pack2(v4.x, v4.x);
            unsigned long long vy = pack2(v4.y, v4.y);
            unsigned long long vz = pack2(v4.z, v4.z);
            unsigned long long vw = pack2(v4.w, v4.w);
            ffma2(acc2[0][0], wA, vx); ffma2(acc2[0][1], wA, vy);
            ffma2(acc2[0][2], wA, vz); ffma2(acc2[0][3], wA, vw);
            ffma2(acc2[1][0], wB, vx); ffma2(acc2[1][1], wB, vy);
            ffma2(acc2[1][2], wB, vz); ffma2(acc2[1][3], wB, vw);
        }
    }

    #pragma unroll
    for (int r = 0; r < 2; r++) {
        float oc[2][4];
        #pragma unroll
        for (int j = 0; j < 4; j++) {
            float2 ab = unpack2(acc2[r][j]);
            oc[0][j] = ab.x; oc[1][j] = ab.y;
        }
        #pragma unroll
        for (int e = 0; e < 2; e++) {
            int o = o0 + 2 * r + e;
            float s1 = g_s1[o], s2 = g_s2[o];
            if (o < 64) {
                float* dst = g_q48 + ((size_t)b * 64 + o) * HW + hw0;
                #pragma unroll
                for (int j = 0; j < 4; j++) {
                    int p = p0 + j;
                    dst[p] = srs[p] * (oc[e][j] - smu[p] * s1) + s2;
                }
            } else {
                int o2 = o - 64, g = o2 >> 5, c = o2 & 31;
                float* dst = g_kT + ((size_t)(b * 2 + g) * HW + hw0) * 32 + c;
                #pragma unroll
                for (int j = 0; j < 4; j++) {
                    int p = p0 + j;
                    dst[p * 32] = srs[p] * (oc[e][j] - smu[p] * s1) + s2;
                }
            }
        }
    }
}

// ---------------- 4. bilinear resize q 48->96, 4 channels/thread ---------
__global__ void k_resize() {   // grid 1152, block 256
    int idx = blockIdx.x * 256 + threadIdx.x;   // < 32*9216
    int p = idx % N1, bc = idx / N1;            // bc in 0..31
    int y = p / OHH, xo = p % OHH;
    float ys = y * SIN;  int y0 = min((int)ys, 46); float wy = ys - (float)y0;
    float xs = xo * SIN; int x0 = min((int)xs, 46); float wx = xs - (float)x0;
    int off = y0 * 48 + x0;
    float wa = (1.f - wy) * (1.f - wx), wb = (1.f - wy) * wx;
    float wc = wy * (1.f - wx),         wd = wy * wx;
    #pragma unroll
    for (int j = 0; j < 4; j++) {
        const float* bp = g_q48 + (size_t)(bc + j * 32) * HW + off;
        g_qup[idx + (size_t)(j * 32) * N1] =
            bp[0] * wa + bp[1] * wb + bp[48] * wc + bp[49] * wd;
    }
}

// ---------------- 5. dwconv3x3 + LN(32) + GELU, 4-way channel split ------
// 256 threads = 64 px x 4 quarters (8 ch each); grid (144, 4)
__global__ void __launch_bounds__(256) k_off1(const float* __restrict__ dww,
                                              const float* __restrict__ og,
                                              const float* __restrict__ ob) {
    __shared__ float ws[288], sg[32], sb[32];
    __shared__ float ps[4][64], pq[4][64];
    int tid = threadIdx.x;
    for (int i = tid; i < 288; i += 256) ws[i] = dww[i];
    if (tid < 32) { sg[tid] = og[tid]; sb[tid] = ob[tid]; }
    __syncthreads();
    int bg = blockIdx.y, b = bg >> 1, g = bg & 1;
    int pl = tid & 63, qt = tid >> 6;
    int p = blockIdx.x * 64 + pl;
    int y = p / OHH, xo = p % OHH;
    int offk[9]; float inbk[9];
    {
        int k = 0;
        #pragma unroll
        for (int dy = -1; dy <= 1; dy++)
            #pragma unroll
            for (int dx = -1; dx <= 1; dx++) {
                bool v = ((unsigned)(y + dy) < 96u) && ((unsigned)(xo + dx) < 96u);
                inbk[k] = v ? 1.f : 0.f;
                offk[k] = v ? (dy * OHH + dx) : 0;
                k++;
            }
    }
    int c0 = qt * 8;
    const float* qb = g_qup + ((size_t)b * 64 + g * 32 + c0) * N1 + p;
    float tc[8];
    float s = 0.f, q = 0.f;
    #pragma unroll
    for (int c = 0; c < 8; c++) {
        const float* pline = qb + (size_t)c * N1;
        const float* wc = ws + (c0 + c) * 9;
        float a = 0.f;
        #pragma unroll
        for (int k = 0; k < 9; k++)
            a = fmaf(wc[k] * inbk[k], pline[offk[k]], a);
        tc[c] = a; s += a; q += a * a;
    }
    ps[qt][pl] = s; pq[qt][pl] = q;
    __syncthreads();
    float S = ps[0][pl] + ps[1][pl] + ps[2][pl] + ps[3][pl];
    float Q = pq[0][pl] + pq[1][pl] + pq[2][pl] + pq[3][pl];
    float mu = S * (1.f / 32.f);
    float rstd = rsqrtf(Q * (1.f / 32.f) - mu * mu + 1e-5f);
    float4* dst = (float4*)(g_t + ((size_t)bg * N1 + p) * 32) + qt * 2;
    #pragma unroll
    for (int c4 = 0; c4 < 2; c4++) {
        float4 o4;
        float* po = (float*)&o4;
        #pragma unroll
        for (int j = 0; j < 4; j++) {
            int c = c4 * 4 + j;
            float tn = (tc[c] - mu) * rstd * sg[c0 + c] + sb[c0 + c];
            po[j] = 0.5f * tn * (1.f + erff(tn * 0.70710678118654752f));
        }
        dst[c4] = o4;
    }
}

// ---------------- 6. conv3x3 32->18 + bias + tanh -> corner tables -------
// 256 threads = 128 pixels x 2 channel-halves; grid (72, 4)
// inner loop uses packed f32x2 FMA over output pairs
__global__ void __launch_bounds__(256) k_off2(const float* __restrict__ ow,
                                              const float* __restrict__ obias) {
    __shared__ float ws2[5184];      // interleaved [k][op][c][2]  (o = 2*op + e)
    __shared__ float bs[18];
    __shared__ float part[18][128];  // half-1 partials
    int tid = threadIdx.x;
    for (int i = tid; i < 5184; i += 256) {
        int o = i / 288, r = i - o * 288;
        int c = r / 9, k = r - c * 9;
        int op = o >> 1, e = o & 1;
        ws2[((k * 9 + op) * 32 + c) * 2 + e] = ow[i];
    }
    if (tid < 18) bs[tid] = obias[tid];
    __syncthreads();
    int bg = blockIdx.y;
    int pl = tid & 127, half = tid >> 7;
    int p = blockIdx.x * 128 + pl;
    int y = p / OHH, xo = p % OHH;
    int offk[9]; bool inbk[9];
    {
        int k = 0;
        #pragma unroll
        for (int dy = -1; dy <= 1; dy++)
            #pragma unroll
            for (int dx = -1; dx <= 1; dx++) {
                bool v = ((unsigned)(y + dy) < 96u) && ((unsigned)(xo + dx) < 96u);
                inbk[k] = v;
                offk[k] = v ? (dy * OHH + dx) : 0;
                k++;
            }
    }
    const float* tb = g_t + (size_t)bg * N1 * 32;
    unsigned long long acc2[9];      // packed (out 2*op, 2*op+1)
    #pragma unroll
    for (int op = 0; op < 9; op++) acc2[op] = 0ull;
    for (int k = 0; k < 9; k++) {
        if (!inbk[k]) continue;
        const float4* vp = (const float4*)(tb + (size_t)(p + offk[k]) * 32) + half * 4;
        float4 v0 = vp[0], v1 = vp[1], v2 = vp[2], v3 = vp[3];
        unsigned long long vs[16];
        vs[0]  = pack2(v0.x, v0.x); vs[1]  = pack2(v0.y, v0.y);
        vs[2]  = pack2(v0.z, v0.z); vs[3]  = pack2(v0.w, v0.w);
        vs[4]  = pack2(v1.x, v1.x); vs[5]  = pack2(v1.y, v1.y);
        vs[6]  = pack2(v1.z, v1.z); vs[7]  = pack2(v1.w, v1.w);
        vs[8]  = pack2(v2.x, v2.x); vs[9]  = pack2(v2.y, v2.y);
        vs[10] = pack2(v2.z, v2.z); vs[11] = pack2(v2.w, v2.w);
        vs[12] = pack2(v3.x, v3.x); vs[13] = pack2(v3.y, v3.y);
        vs[14] = pack2(v3.z, v3.z); vs[15] = pack2(v3.w, v3.w);
        #pragma unroll
        for (int op = 0; op < 9; op++) {
            const unsigned long long* wp =
                (const unsigned long long*)(ws2 + ((k * 9 + op) * 32 + half * 16) * 2);
            #pragma unroll
            for (int c = 0; c < 16; c++)
                ffma2(acc2[op], wp[c], vs[c]);
        }
    }
    float acc[18];
    #pragma unroll
    for (int op = 0; op < 9; op++) {
        float2 ab = unpack2(acc2[op]);
        acc[2 * op] = ab.x; acc[2 * op + 1] = ab.y;
    }
    if (half == 1) {
        #pragma unroll
        for (int o = 0; o < 18; o++) part[o][pl] = acc[o];
    }
    __syncthreads();
    if (half == 0) {
        #pragma unroll
        for (int o = 0; o < 18; o++) acc[o] += part[o][pl];
        #pragma unroll
        for (int kk = 0; kk < 9; kk++) {
            int ky = kk / 3, kx = kk % 3;
            float ey = tanhf(acc[2 * kk]     + bs[2 * kk])     * RFf + (float)(ky - 1) + (float)y;
            float ex = tanhf(acc[2 * kk + 1] + bs[2 * kk + 1]) * RFf + (float)(kx - 1) + (float)xo;
            Corner cr = mk_corner(ey * SIN, ex * SIN);
            size_t o = (size_t)(bg * NK + kk) * N1 + p;
            g_ci[o] = make_int4(cr.i00 * 32, cr.i01 * 32, cr.i10 * 32, cr.i11 * 32);
            g_cw[o] = make_float4(cr.w00, cr.w01, cr.w10, cr.w11);
        }
    }
}

// ---------------- 7. fused deformable gather + attention -----------------
// smem-staged q / corner tables; fp16 V; K-gather decoupled from reduce
__global__ void __launch_bounds__(256) k_attn(const float* __restrict__ rpb,
                                              float* __restrict__ out) {
    __shared__ float  rp[288];
    __shared__ float  qs[32 * 33];    // [c][p]
    __shared__ int4   cis[9][32];
    __shared__ float4 cws[9][32];
    __shared__ float  obuf[32 * 129];
    int tid = threadIdx.x;
    int b = blockIdx.z, h = blockIdx.y, bg = b * 2 + h;
    int tr = blockIdx.x / 3, tc3 = blockIdx.x % 3;
    int gy0 = tr * 4, gx0 = tc3 * 32;     // 4-row x 32-col output tile

    for (int i = tid; i < 288; i += 256) rp[i] = rpb[h * 288 + i];

    int lane = tid & 31, w = tid >> 5;
    const float* kb = g_kT + (size_t)bg * HW * 32;
    const uint2* vb = (const uint2*)(g_vTh + (size_t)bg * HW * 128);  // 4 halves/lane
    const float* qbase = g_qup + (size_t)(b * 64 + h * 32) * N1;
    const int4*   cib = g_ci + (size_t)bg * NK * N1;
    const float4* cwb = g_cw + (size_t)bg * NK * N1;

    for (int rr = 0; rr < 4; rr++) {
        int prow = (gy0 + rr) * 96 + gx0;
        __syncthreads();
        for (int idx = tid; idx < 1024; idx += 256) {
            int c = idx >> 5, p = idx & 31;
            qs[c * 33 + p] = qbase[(size_t)c * N1 + prow + p] * SCLQ;
        }
        for (int idx = tid; idx < 288; idx += 256) {
            int kk = idx >> 5, p = idx & 31;
            cis[kk][p] = cib[(size_t)kk * N1 + prow + p];
            cws[kk][p] = cwb[(size_t)kk * N1 + prow + p];
        }
        __syncthreads();

        #pragma unroll
        for (int j = 0; j < 4; j++) {
            int pl = j * 8 + w;
            float qv = qs[lane * 33 + pl];

            // Phase 1: batched K gather (36 independent LDGs before any reduce)
            float kvv[9];
            #pragma unroll
            for (int kk = 0; kk < 9; kk++) {
                int4   pi = cis[kk][pl];
                float4 pw = cws[kk][pl];
                kvv[kk] = pw.x * kb[pi.x + lane]
                        + pw.y * kb[pi.y + lane]
                        + pw.z * kb[pi.z + lane]
                        + pw.w * kb[pi.w + lane];
            }
            // Phase 2: reduce chains (shfl latency overlapped across taps)
            float lg[9];
            #pragma unroll
            for (int kk = 0; kk < 9; kk++) {
                float pt = qv * (kvv[kk] + rp[kk * 32 + lane]);
                #pragma unroll
                for (int o = 16; o; o >>= 1) pt += __shfl_xor_sync(0xffffffffu, pt, o);
                lg[kk] = pt;
            }
            float m = lg[0];
            #pragma unroll
            for (int kk = 1; kk < 9; kk++) m = fmaxf(m, lg[kk]);
            float s = 0.f;
            #pragma unroll
            for (int kk = 0; kk < 9; kk++) { lg[kk] = __expf(lg[kk] - m); s += lg[kk]; }
            float inv = 1.f / s;

            float4 acc = make_float4(0.f, 0.f, 0.f, 0.f);
            #pragma unroll
            for (int kk = 0; kk < 9; kk++) {
                int4   pi = cis[kk][pl];
                float4 pw = cws[kk][pl];
                float a = lg[kk] * inv;
                float a00 = a * pw.x, a01 = a * pw.y, a10 = a * pw.z, a11 = a * pw.w;
                uint2 r0 = vb[pi.x + lane];
                uint2 r1 = vb[pi.y + lane];
                uint2 r2 = vb[pi.z + lane];
                uint2 r3 = vb[pi.w + lane];
                float2 f0a = __half22float2(*(const __half2*)&r0.x);
                float2 f0b = __half22float2(*(const __half2*)&r0.y);
                float2 f1a = __half22float2(*(const __half2*)&r1.x);
                float2 f1b = __half22float2(*(const __half2*)&r1.y);
                float2 f2a = __half22float2(*(const __half2*)&r2.x);
                float2 f2b = __half22float2(*(const __half2*)&r2.y);
                float2 f3a = __half22float2(*(const __half2*)&r3.x);
                float2 f3b = __half22float2(*(const __half2*)&r3.y);
                acc.x += a00 * f0a.x + a01 * f1a.x + a10 * f2a.x + a11 * f3a.x;
                acc.y += a00 * f0a.y + a01 * f1a.y + a10 * f2a.y + a11 * f3a.y;
                acc.z += a00 * f0b.x + a01 * f1b.x + a10 * f2b.x + a11 * f3b.x;
                acc.w += a00 * f0b.y + a01 * f1b.y + a10 * f2b.y + a11 * f3b.y;
            }
            float* o4 = obuf + pl * 129 + lane * 4;
            o4[0] = acc.x; o4[1] = acc.y; o4[2] = acc.z; o4[3] = acc.w;
        }
        __syncthreads();
        float* ob = out + ((size_t)(b * 256 + h * 128)) * N1 + prow;
        for (int idx = tid; idx < 4096; idx += 256) {
            int c2 = idx >> 5, cc = idx & 31;
            ob[(size_t)c2 * N1 + cc] = obuf[cc * 129 + c2];
        }
    }
}

// ---------------- launch --------------------------------------------------
extern "C" void kernel_launch(void* const* d_in, const int* in_sizes, int n_in,
                              void* d_out, int out_size) {
    const float* x    = (const float*)d_in[0];
    const float* ln_g = (const float*)d_in[1];
    const float* ln_b = (const float*)d_in[2];
    const float* Wq   = (const float*)d_in[3];
    const float* Wk   = (const float*)d_in[4];
    const float* dww  = (const float*)d_in[5];
    const float* olg  = (const float*)d_in[6];
    const float* olb  = (const float*)d_in[7];
    const float* ow   = (const float*)d_in[8];
    const float* obb  = (const float*)d_in[9];
    const float* rpb  = (const float*)d_in[10];
    float* out = (float*)d_out;

    k_prep  <<<128, 256>>>(Wq, Wk, ln_g, ln_b);
    k_vt    <<<dim3(72, 4, 4), dim3(32, 8)>>>(x);
    k_proj  <<<144, 256>>>(x);
    k_resize<<<1152, 256>>>();
    k_off1  <<<dim3(144, 4), 256>>>(dww, olg, olb);
    k_off2  <<<dim3(72, 4), 256>>>(ow, obb);
    k_attn  <<<dim3(72, 2, 2), 256>>>(rpb, out);
}